// round 3
// baseline (speedup 1.0000x reference)
#include <cuda_runtime.h>

// out = inputs * (noise >= 0.5f ? 2.0f : 0.0f)
// 67,108,864 fp32 = 16,777,216 float4 = 32768 blocks * 256 threads * 2 vec4/thread.
// VPT=2: MLP=4 front-batched loads, low register count (keeps occupancy ~78%),
// evict-first cache hints (pure streaming, zero reuse).

__global__ void __launch_bounds__(256)
sparse_dropout_vec4x2(const float4* __restrict__ inputs,
                      const float4* __restrict__ noise,
                      float4* __restrict__ out)
{
    const unsigned base = blockIdx.x * (blockDim.x * 2) + threadIdx.x;

    // Front-batch 4 independent LDG.128
    float4 x0 = __ldcs(&inputs[base]);
    float4 x1 = __ldcs(&inputs[base + 256]);
    float4 n0 = __ldcs(&noise[base]);
    float4 n1 = __ldcs(&noise[base + 256]);

    float4 r0, r1;
    r0.x = (n0.x >= 0.5f) ? x0.x * 2.0f : 0.0f;
    r0.y = (n0.y >= 0.5f) ? x0.y * 2.0f : 0.0f;
    r0.z = (n0.z >= 0.5f) ? x0.z * 2.0f : 0.0f;
    r0.w = (n0.w >= 0.5f) ? x0.w * 2.0f : 0.0f;

    r1.x = (n1.x >= 0.5f) ? x1.x * 2.0f : 0.0f;
    r1.y = (n1.y >= 0.5f) ? x1.y * 2.0f : 0.0f;
    r1.z = (n1.z >= 0.5f) ? x1.z * 2.0f : 0.0f;
    r1.w = (n1.w >= 0.5f) ? x1.w * 2.0f : 0.0f;

    __stcs(&out[base],       r0);
    __stcs(&out[base + 256], r1);
}

extern "C" void kernel_launch(void* const* d_in, const int* in_sizes, int n_in,
                              void* d_out, int out_size)
{
    const float4* inputs = (const float4*)d_in[0];
    const float4* noise  = (const float4*)d_in[1];
    float4* out          = (float4*)d_out;

    const int n_vec4 = out_size / 4;          // 16,777,216
    const int threads = 256;
    const int blocks = n_vec4 / (threads * 2); // 32768, exact

    sparse_dropout_vec4x2<<<blocks, threads>>>(inputs, noise, out);
}

// round 4
// speedup vs baseline: 1.0309x; 1.0309x over previous
#include <cuda_runtime.h>

// out = inputs * (noise >= 0.5f ? 2.0f : 0.0f)
// 67,108,864 fp32 = 16,777,216 float4 = 32768 blocks * 512 threads * 1 vec4/thread.
// R1 structure (VPT=1, plain cached loads/stores — hints measured harmful),
// 512-thread blocks for 8KiB-contiguous per-block footprint per array.

__global__ void __launch_bounds__(512)
sparse_dropout_vec4_b512(const float4* __restrict__ inputs,
                         const float4* __restrict__ noise,
                         float4* __restrict__ out)
{
    const unsigned idx = blockIdx.x * blockDim.x + threadIdx.x;

    float4 x = inputs[idx];
    float4 n = noise[idx];

    float4 r;
    r.x = (n.x >= 0.5f) ? x.x * 2.0f : 0.0f;
    r.y = (n.y >= 0.5f) ? x.y * 2.0f : 0.0f;
    r.z = (n.z >= 0.5f) ? x.z * 2.0f : 0.0f;
    r.w = (n.w >= 0.5f) ? x.w * 2.0f : 0.0f;

    out[idx] = r;
}

extern "C" void kernel_launch(void* const* d_in, const int* in_sizes, int n_in,
                              void* d_out, int out_size)
{
    const float4* inputs = (const float4*)d_in[0];
    const float4* noise  = (const float4*)d_in[1];
    float4* out          = (float4*)d_out;

    const int n_vec4 = out_size / 4;     // 16,777,216
    const int threads = 512;
    const int blocks = n_vec4 / threads; // 32768, exact

    sparse_dropout_vec4_b512<<<blocks, threads>>>(inputs, noise, out);
}